// round 16
// baseline (speedup 1.0000x reference)
#include <cuda_runtime.h>
#include <cuda_fp16.h>
#include <math.h>
#include <math_constants.h>

#define NMAX 100000
#define EMAX 1600000
#define D 128
#define NHEAD 4

// packed fp32x2 FMA (Blackwell): exact fp32 FMA semantics per half.
#define FMA_F32X2(d, a, b, c) \
    asm("fma.rn.f32x2 %0, %1, %2, %3;" : "=l"(d) : "l"(a), "l"(b), "l"(c))

// ---------------- static scratch (allowed: __device__ globals) ----------------
__device__ __half2 g_h[(size_t)NMAX * 64];     // transformed features [N,128] as fp16
__device__ float g_asrc[NMAX * NHEAD];         // per-node src attention term (fp32)
__device__ float g_adst[NMAX * NHEAD];         // per-node dst attention term (fp32)
__device__ int   g_src[EMAX];
__device__ int   g_dst[EMAX];
__device__ int   g_rank[EMAX];                 // arrival rank among edges sharing dst
__device__ int   g_deg[NMAX];
__device__ int   g_off[NMAX];                  // block-LOCAL exclusive offsets (scan1)
__device__ int   g_csr[EMAX];                  // src node per incoming edge, grouped by dst
__device__ int   g_bsum[1024];                 // block prefix sums (scan2)
__device__ int   g_is64;

// ---------------- detect dtype (int64 vs int32) + zero degree array ----------------
__global__ void k_detect_zero(const void* ei, int n) {
    int gid = blockIdx.x * blockDim.x + threadIdx.x;
    if (gid == 0) {
        const unsigned int* w = (const unsigned int*)ei;
        int all0 = 1;
        #pragma unroll
        for (int k = 0; k < 64; k++)
            if (w[2 * k + 1] != 0u) all0 = 0;
        g_is64 = all0;  // values < 2^31 and nonneg -> high word zero iff int64
    }
    if (gid < n) g_deg[gid] = 0;
}

// extract src/dst, count degree, remember per-edge rank
__global__ void k_extract(const void* ei, int E) {
    int i = blockIdx.x * blockDim.x + threadIdx.x;
    if (i >= E) return;
    int s, d;
    if (g_is64) {
        const long long* p = (const long long*)ei;
        s = (int)p[i]; d = (int)p[E + i];
    } else {
        const int* p = (const int*)ei;
        s = p[i]; d = p[E + i];
    }
    g_src[i] = s; g_dst[i] = d;
    g_rank[i] = atomicAdd(&g_deg[d], 1);
}

// ---------------- hierarchical exclusive scan of degrees ----------------
__global__ void k_scan1(int n) {
    __shared__ int wsum[32];
    int tid = threadIdx.x;
    int gid = blockIdx.x * 1024 + tid;
    int v = (gid < n) ? g_deg[gid] : 0;
    int lane = tid & 31, wid = tid >> 5;
    int xv = v;
    #pragma unroll
    for (int o = 1; o < 32; o <<= 1) {
        int t = __shfl_up_sync(0xffffffffu, xv, o);
        if (lane >= o) xv += t;
    }
    if (lane == 31) wsum[wid] = xv;
    __syncthreads();
    if (wid == 0) {
        int s = wsum[lane];
        #pragma unroll
        for (int o = 1; o < 32; o <<= 1) {
            int t = __shfl_up_sync(0xffffffffu, s, o);
            if (lane >= o) s += t;
        }
        wsum[lane] = s;
    }
    __syncthreads();
    int incl = xv + (wid ? wsum[wid - 1] : 0);
    if (gid < n) g_off[gid] = incl - v;
    if (tid == 1023) g_bsum[blockIdx.x] = incl;
}

__global__ void k_scan2(int B) {
    __shared__ int wsum[32];
    int tid = threadIdx.x;
    int v = (tid < B) ? g_bsum[tid] : 0;
    int lane = tid & 31, wid = tid >> 5;
    int xv = v;
    #pragma unroll
    for (int o = 1; o < 32; o <<= 1) {
        int t = __shfl_up_sync(0xffffffffu, xv, o);
        if (lane >= o) xv += t;
    }
    if (lane == 31) wsum[wid] = xv;
    __syncthreads();
    if (wid == 0) {
        int s = wsum[lane];
        #pragma unroll
        for (int o = 1; o < 32; o <<= 1) {
            int t = __shfl_up_sync(0xffffffffu, s, o);
            if (lane >= o) s += t;
        }
        wsum[lane] = s;
    }
    __syncthreads();
    int incl = xv + (wid ? wsum[wid - 1] : 0);
    if (tid < B) g_bsum[tid] = incl - v;
}

// atomic-free scatter; final offset = local off + block prefix (scan3 fused)
__global__ void k_scatter(int E) {
    int i = blockIdx.x * blockDim.x + threadIdx.x;
    if (i >= E) return;
    int d = g_dst[i];
    g_csr[g_off[d] + __ldg(&g_bsum[d >> 10]) + g_rank[i]] = g_src[i];
}

// ---------------- GEMM: h = x @ W (fp32 FFMA2), fp16 store, fused att dots ----
// K tiled by 32; x staged as duplicated pairs so the mainloop needs no MOV
// packs: per k = 1 LDS.128 (W channel-pairs) + 8 broadcast LDS.64 + 16 FFMA2
// (25 issues vs R10's 34). Static smem 32KB keeps 4 blocks/SM occupancy.
__global__ void __launch_bounds__(256)
k_gemm(const float* __restrict__ x, const float* __restrict__ W,
       const float* __restrict__ att_src, const float* __restrict__ att_dst,
       int n) {
    __shared__ float ws[32 * 128];     // 16KB: W rows kt*32..+31, all 128 channels
    __shared__ float xs2f[64 * 32 * 2];// 16KB: x tile [64 r][32 k] duplicated pairs
    int tid = threadIdx.x;
    int r0 = blockIdx.x * 64;
    int w = tid >> 5;
    int l = tid & 31;

    unsigned long long accA[8], accB[8];
    #pragma unroll
    for (int i = 0; i < 8; i++) { accA[i] = 0ull; accB[i] = 0ull; }

    for (int kt = 0; kt < 4; kt++) {
        // W rows kt*32..+31 (1024 float4, coalesced)
        for (int i = tid; i < 1024; i += 256)
            ((float4*)ws)[i] = ((const float4*)W)[(kt * 32) * 32 + i];
        // x tile [64][32] -> duplicated pairs (x,x) per k
        for (int i = tid; i < 512; i += 256) {
            int r = i >> 3, c4 = i & 7;
            float4 v = make_float4(0.f, 0.f, 0.f, 0.f);
            if (r0 + r < n) v = ((const float4*)x)[(size_t)(r0 + r) * 32 + kt * 8 + c4];
            int b = (r * 32 + c4 * 4) * 2;
            xs2f[b + 0] = v.x; xs2f[b + 1] = v.x;
            xs2f[b + 2] = v.y; xs2f[b + 3] = v.y;
            xs2f[b + 4] = v.z; xs2f[b + 5] = v.z;
            xs2f[b + 6] = v.w; xs2f[b + 7] = v.w;
        }
        __syncthreads();

        const ulonglong2* wrow2 = (const ulonglong2*)ws;   // [k][32 pair-of-pairs]
        const unsigned long long* xp = (const unsigned long long*)xs2f;
        #pragma unroll 4
        for (int k = 0; k < 32; k++) {
            ulonglong2 wv = wrow2[k * 32 + l];   // channels 4l..4l+3 (one LDS.128)
            #pragma unroll
            for (int i = 0; i < 8; i++) {
                unsigned long long xv2 = xp[(w * 8 + i) * 32 + k];  // bcast LDS.64
                FMA_F32X2(accA[i], xv2, wv.x, accA[i]);
                FMA_F32X2(accB[i], xv2, wv.y, accB[i]);
            }
        }
        __syncthreads();
    }

    float4 asv = __ldg(((const float4*)att_src) + l);
    float4 adv = __ldg(((const float4*)att_dst) + l);
    int head = l >> 3;
    #pragma unroll
    for (int i = 0; i < 8; i++) {
        int r = r0 + w * 8 + i;
        if (r < n) {
            float a0 = __uint_as_float((unsigned int)(accA[i] & 0xffffffffu));
            float a1 = __uint_as_float((unsigned int)(accA[i] >> 32));
            float a2 = __uint_as_float((unsigned int)(accB[i] & 0xffffffffu));
            float a3 = __uint_as_float((unsigned int)(accB[i] >> 32));
            __half2 h01 = __floats2half2_rn(a0, a1);
            __half2 h23 = __floats2half2_rn(a2, a3);
            uint2 hv;
            hv.x = *(unsigned int*)&h01;
            hv.y = *(unsigned int*)&h23;
            ((uint2*)(g_h + (size_t)r * 64))[l] = hv;
            float ps = a0*asv.x + a1*asv.y + a2*asv.z + a3*asv.w;
            float pd = a0*adv.x + a1*adv.y + a2*adv.z + a3*adv.w;
            #pragma unroll
            for (int o = 1; o < 8; o <<= 1) {
                ps += __shfl_xor_sync(0xffffffffu, ps, o);
                pd += __shfl_xor_sync(0xffffffffu, pd, o);
            }
            if ((l & 7) == 0) {
                g_asrc[r * NHEAD + head] = ps;
                g_adst[r * NHEAD + head] = pd;
            }
        }
    }
}

// ---------------- warp-per-node fused (exact R10 structure): softmax gather
//                  (fp16 h) + LN + PReLU + residual ----------------
// Lane l owns channels 4l..4l+3 (all within head l>>3). 8 warps/block = 8 nodes.
// No max-subtraction (logits O(10), exp far from overflow; alpha identical).
__global__ void __launch_bounds__(256)
k_node(const float* __restrict__ x, const float* __restrict__ bias,
       const float* __restrict__ gamma, const float* __restrict__ beta,
       const float* __restrict__ prelu_w, float* __restrict__ out, int n) {
    __shared__ float4 wv_s[8][32];   // per-warp staged edge weights (4 heads)
    __shared__ int    ss_s[8][32];   // per-warp staged src ids

    int tid = threadIdx.x;
    int lane = tid & 31, w = tid >> 5;
    int node = blockIdx.x * 8 + w;
    if (node >= n) return;

    int head = lane >> 3;

    float4 bs = __ldg(((const float4*)bias) + lane);
    float4 gm = __ldg(((const float4*)gamma) + lane);
    float4 bt = __ldg(((const float4*)beta) + lane);
    float pw  = __ldg(prelu_w);

    int beg = g_off[node] + __ldg(&g_bsum[node >> 10]);   // scan3 fused here
    int deg = g_deg[node];
    float4 ad = __ldg((const float4*)(g_adst + node * NHEAD));  // warp-uniform sector

    float den = 0.f;
    float4 acc = make_float4(0.f, 0.f, 0.f, 0.f);

    for (int base = 0; base < deg; base += 32) {
        int cn = min(32, deg - base);
        if (lane < cn) {
            int s = __ldg(&g_csr[beg + base + lane]);
            float4 av = __ldg((const float4*)(g_asrc + s * NHEAD));
            float l0 = av.x + ad.x; l0 = l0 >= 0.f ? l0 : 0.2f * l0;
            float l1 = av.y + ad.y; l1 = l1 >= 0.f ? l1 : 0.2f * l1;
            float l2 = av.z + ad.z; l2 = l2 >= 0.f ? l2 : 0.2f * l2;
            float l3 = av.w + ad.w; l3 = l3 >= 0.f ? l3 : 0.2f * l3;
            wv_s[w][lane] = make_float4(__expf(l0), __expf(l1), __expf(l2), __expf(l3));
            ss_s[w][lane] = s;
        }
        __syncwarp();
        #pragma unroll 16
        for (int j = 0; j < cn; j++) {
            int s = ss_s[w][j];                               // smem broadcast
            float a = ((const float*)&wv_s[w][j])[head];      // smem (4-way bcast)
            uint2 hv = __ldg(((const uint2*)(g_h + (size_t)s * 64)) + lane); // 256B/warp
            float2 f01 = __half22float2(*(__half2*)&hv.x);
            float2 f23 = __half22float2(*(__half2*)&hv.y);
            den += a;
            acc.x += a * f01.x; acc.y += a * f01.y;
            acc.z += a * f23.x; acc.w += a * f23.y;
        }
        if (base + 32 < deg) __syncwarp();
    }

    float inv = (den > 0.f) ? (1.f / den) : 0.f;   // deg==0 -> 0 (matches ref)

    // LayerNorm over the warp's 128 channels (4 per lane)
    float4 v;
    v.x = acc.x * inv + bs.x; v.y = acc.y * inv + bs.y;
    v.z = acc.z * inv + bs.z; v.w = acc.w * inv + bs.w;
    float s1 = v.x + v.y + v.z + v.w;
    float s2 = v.x * v.x + v.y * v.y + v.z * v.z + v.w * v.w;
    #pragma unroll
    for (int o = 16; o > 0; o >>= 1) {
        s1 += __shfl_xor_sync(0xffffffffu, s1, o);
        s2 += __shfl_xor_sync(0xffffffffu, s2, o);
    }
    float mu = s1 * (1.f / 128.f);
    float var = fmaxf(s2 * (1.f / 128.f) - mu * mu, 0.f);
    float rs = rsqrtf(var + 1e-5f);

    float4 xv = __ldg(((const float4*)(x + (size_t)node * D)) + lane);
    float4 o4;
    float o;
    o = (v.x - mu) * rs * gm.x + bt.x; o = o >= 0.f ? o : pw * o; o4.x = o + xv.x;
    o = (v.y - mu) * rs * gm.y + bt.y; o = o >= 0.f ? o : pw * o; o4.y = o + xv.y;
    o = (v.z - mu) * rs * gm.z + bt.z; o = o >= 0.f ? o : pw * o; o4.z = o + xv.z;
    o = (v.w - mu) * rs * gm.w + bt.w; o = o >= 0.f ? o : pw * o; o4.w = o + xv.w;
    ((float4*)(out + (size_t)node * D))[lane] = o4;
}

// ---------------- launch: fork GEMM onto side stream, overlap with CSR build ----
extern "C" void kernel_launch(void* const* d_in, const int* in_sizes, int n_in,
                              void* d_out, int out_size) {
    const float* x       = (const float*)d_in[0];
    const void*  ei      = d_in[1];
    const float* W       = (const float*)d_in[2];
    const float* att_src = (const float*)d_in[3];
    const float* att_dst = (const float*)d_in[4];
    const float* bias    = (const float*)d_in[5];
    const float* gamma   = (const float*)d_in[6];
    const float* beta    = (const float*)d_in[7];
    const float* prelu   = (const float*)d_in[8];
    float* out = (float*)d_out;

    int n = in_sizes[0] / D;
    int E = in_sizes[1] / 2;
    int B = (n + 1023) / 1024;

    static cudaStream_t s2 = 0;
    static cudaEvent_t evFork = 0, evJoin = 0;
    static int init = 0;
    if (!init) {
        if (cudaStreamCreateWithFlags(&s2, cudaStreamNonBlocking) != cudaSuccess) s2 = 0;
        cudaEventCreateWithFlags(&evFork, cudaEventDisableTiming);
        cudaEventCreateWithFlags(&evJoin, cudaEventDisableTiming);
        init = 1;
    }

    bool fork = (s2 != 0);
    if (fork) {
        cudaEventRecord(evFork, 0);
        cudaStreamWaitEvent(s2, evFork, 0);
        k_gemm<<<(n + 63) / 64, 256, 0, s2>>>(x, W, att_src, att_dst, n);
        cudaEventRecord(evJoin, s2);
    }

    k_detect_zero<<<(n + 255) / 256, 256>>>(ei, n);
    k_extract<<<(E + 255) / 256, 256>>>(ei, E);
    k_scan1<<<B, 1024>>>(n);
    k_scan2<<<1, 1024>>>(B);
    k_scatter<<<(E + 255) / 256, 256>>>(E);

    if (fork) {
        cudaStreamWaitEvent(0, evJoin, 0);   // join before consumers of g_h/g_asrc
    } else {
        k_gemm<<<(n + 63) / 64, 256>>>(x, W, att_src, att_dst, n);
    }

    k_node<<<(n + 7) / 8, 256>>>(x, bias, gamma, beta, prelu, out, n);
}

// round 17
// speedup vs baseline: 1.5866x; 1.5866x over previous
#include <cuda_runtime.h>
#include <cuda_fp16.h>
#include <math.h>
#include <math_constants.h>

#define NMAX 100000
#define EMAX 1600000
#define D 128
#define NHEAD 4

// packed fp32x2 FMA (Blackwell): exact fp32 FMA semantics per half.
#define FMA_F32X2(d, a, b, c) \
    asm("fma.rn.f32x2 %0, %1, %2, %3;" : "=l"(d) : "l"(a), "l"(b), "l"(c))
#define PACK_BCAST(d, r) \
    asm("mov.b64 %0, {%1, %1};" : "=l"(d) : "r"(r))

// ---------------- static scratch (allowed: __device__ globals) ----------------
__device__ __half2 g_h[(size_t)NMAX * 64];     // transformed features [N,128] as fp16
__device__ float g_asrc[NMAX * NHEAD];         // per-node src attention term (fp32)
__device__ float g_adst[NMAX * NHEAD];         // per-node dst attention term (fp32)
__device__ int   g_src[EMAX];
__device__ int   g_dst[EMAX];
__device__ int   g_rank[EMAX];                 // arrival rank among edges sharing dst
__device__ int   g_deg[NMAX];
__device__ int   g_off[NMAX];                  // block-LOCAL exclusive offsets (scan1)
__device__ int   g_csr[EMAX];                  // src node per incoming edge, grouped by dst
__device__ int   g_bsum[1024];                 // block prefix sums (scan2)
__device__ int   g_is64;

// ---------------- detect dtype (int64 vs int32) + zero degree array ----------------
__global__ void k_detect_zero(const void* ei, int n) {
    int gid = blockIdx.x * blockDim.x + threadIdx.x;
    if (gid == 0) {
        const unsigned int* w = (const unsigned int*)ei;
        int all0 = 1;
        #pragma unroll
        for (int k = 0; k < 64; k++)
            if (w[2 * k + 1] != 0u) all0 = 0;
        g_is64 = all0;  // values < 2^31 and nonneg -> high word zero iff int64
    }
    if (gid < n) g_deg[gid] = 0;
}

// extract src/dst, count degree, remember per-edge rank
__global__ void k_extract(const void* ei, int E) {
    int i = blockIdx.x * blockDim.x + threadIdx.x;
    if (i >= E) return;
    int s, d;
    if (g_is64) {
        const long long* p = (const long long*)ei;
        s = (int)p[i]; d = (int)p[E + i];
    } else {
        const int* p = (const int*)ei;
        s = p[i]; d = p[E + i];
    }
    g_src[i] = s; g_dst[i] = d;
    g_rank[i] = atomicAdd(&g_deg[d], 1);
}

// ---------------- hierarchical exclusive scan of degrees ----------------
__global__ void k_scan1(int n) {
    __shared__ int wsum[32];
    int tid = threadIdx.x;
    int gid = blockIdx.x * 1024 + tid;
    int v = (gid < n) ? g_deg[gid] : 0;
    int lane = tid & 31, wid = tid >> 5;
    int xv = v;
    #pragma unroll
    for (int o = 1; o < 32; o <<= 1) {
        int t = __shfl_up_sync(0xffffffffu, xv, o);
        if (lane >= o) xv += t;
    }
    if (lane == 31) wsum[wid] = xv;
    __syncthreads();
    if (wid == 0) {
        int s = wsum[lane];
        #pragma unroll
        for (int o = 1; o < 32; o <<= 1) {
            int t = __shfl_up_sync(0xffffffffu, s, o);
            if (lane >= o) s += t;
        }
        wsum[lane] = s;
    }
    __syncthreads();
    int incl = xv + (wid ? wsum[wid - 1] : 0);
    if (gid < n) g_off[gid] = incl - v;
    if (tid == 1023) g_bsum[blockIdx.x] = incl;
}

__global__ void k_scan2(int B) {
    __shared__ int wsum[32];
    int tid = threadIdx.x;
    int v = (tid < B) ? g_bsum[tid] : 0;
    int lane = tid & 31, wid = tid >> 5;
    int xv = v;
    #pragma unroll
    for (int o = 1; o < 32; o <<= 1) {
        int t = __shfl_up_sync(0xffffffffu, xv, o);
        if (lane >= o) xv += t;
    }
    if (lane == 31) wsum[wid] = xv;
    __syncthreads();
    if (wid == 0) {
        int s = wsum[lane];
        #pragma unroll
        for (int o = 1; o < 32; o <<= 1) {
            int t = __shfl_up_sync(0xffffffffu, s, o);
            if (lane >= o) s += t;
        }
        wsum[lane] = s;
    }
    __syncthreads();
    int incl = xv + (wid ? wsum[wid - 1] : 0);
    if (tid < B) g_bsum[tid] = incl - v;
}

// atomic-free scatter; final offset = local off + block prefix (scan3 fused)
__global__ void k_scatter(int E) {
    int i = blockIdx.x * blockDim.x + threadIdx.x;
    if (i >= E) return;
    int d = g_dst[i];
    g_csr[g_off[d] + __ldg(&g_bsum[d >> 10]) + g_rank[i]] = g_src[i];
}

// ---------------- GEMM: h = x @ W (fp32 FFMA2), fp16 store, fused att dots ----
// (Exact R10 structure — proven 210.7us; do not restructure.)
__global__ void k_gemm(const float* __restrict__ x, const float* __restrict__ W,
                       const float* __restrict__ att_src, const float* __restrict__ att_dst,
                       int n) {
    __shared__ float ws[64 * 128];   // 32KB
    __shared__ float xs[64 * 64];    // 16KB
    int tid = threadIdx.x;
    int r0 = blockIdx.x * 64;
    int w = tid >> 5;
    int l = tid & 31;

    unsigned long long accA[8], accB[8];
    #pragma unroll
    for (int i = 0; i < 8; i++) { accA[i] = 0ull; accB[i] = 0ull; }

    for (int kt = 0; kt < 2; kt++) {
        for (int i = tid; i < 2048; i += 256)
            ((float4*)ws)[i] = ((const float4*)W)[(kt * 64) * 32 + i];
        for (int i = tid; i < 1024; i += 256) {
            int r = i >> 4, c4 = i & 15;
            float4 v = make_float4(0.f, 0.f, 0.f, 0.f);
            if (r0 + r < n) v = ((const float4*)x)[(size_t)(r0 + r) * 32 + kt * 16 + c4];
            ((float4*)xs)[i] = v;
        }
        __syncthreads();
        const float* xrow = xs + w * 8 * 64;
        const unsigned long long* wrow = (const unsigned long long*)(ws);
        #pragma unroll 4
        for (int k = 0; k < 64; k++) {
            unsigned long long wv01 = wrow[k * 64 + 2 * l];
            unsigned long long wv23 = wrow[k * 64 + 2 * l + 1];
            #pragma unroll
            for (int i = 0; i < 8; i++) {
                unsigned int xb = __float_as_uint(xrow[i * 64 + k]);
                unsigned long long xv2;
                PACK_BCAST(xv2, xb);
                FMA_F32X2(accA[i], xv2, wv01, accA[i]);
                FMA_F32X2(accB[i], xv2, wv23, accB[i]);
            }
        }
        __syncthreads();
    }

    float4 asv = __ldg(((const float4*)att_src) + l);
    float4 adv = __ldg(((const float4*)att_dst) + l);
    int head = l >> 3;
    #pragma unroll
    for (int i = 0; i < 8; i++) {
        int r = r0 + w * 8 + i;
        if (r < n) {
            float a0 = __uint_as_float((unsigned int)(accA[i] & 0xffffffffu));
            float a1 = __uint_as_float((unsigned int)(accA[i] >> 32));
            float a2 = __uint_as_float((unsigned int)(accB[i] & 0xffffffffu));
            float a3 = __uint_as_float((unsigned int)(accB[i] >> 32));
            __half2 h01 = __floats2half2_rn(a0, a1);
            __half2 h23 = __floats2half2_rn(a2, a3);
            uint2 hv;
            hv.x = *(unsigned int*)&h01;
            hv.y = *(unsigned int*)&h23;
            ((uint2*)(g_h + (size_t)r * 64))[l] = hv;
            float ps = a0*asv.x + a1*asv.y + a2*asv.z + a3*asv.w;
            float pd = a0*adv.x + a1*adv.y + a2*adv.z + a3*adv.w;
            #pragma unroll
            for (int o = 1; o < 8; o <<= 1) {
                ps += __shfl_xor_sync(0xffffffffu, ps, o);
                pd += __shfl_xor_sync(0xffffffffu, pd, o);
            }
            if ((l & 7) == 0) {
                g_asrc[r * NHEAD + head] = ps;
                g_adst[r * NHEAD + head] = pd;
            }
        }
    }
}

// ---------------- warp-per-node fused (exact R10 structure + hoisted residual) ----
// Lane l owns channels 4l..4l+3 (all within head l>>3). 8 warps/block = 8 nodes.
// No max-subtraction (logits O(10), exp far from overflow; alpha identical).
__global__ void __launch_bounds__(256)
k_node(const float* __restrict__ x, const float* __restrict__ bias,
       const float* __restrict__ gamma, const float* __restrict__ beta,
       const float* __restrict__ prelu_w, float* __restrict__ out, int n) {
    __shared__ float4 wv_s[8][32];   // per-warp staged edge weights (4 heads)
    __shared__ int    ss_s[8][32];   // per-warp staged src ids

    int tid = threadIdx.x;
    int lane = tid & 31, w = tid >> 5;
    int node = blockIdx.x * 8 + w;
    if (node >= n) return;

    int head = lane >> 3;

    float4 bs = __ldg(((const float4*)bias) + lane);
    float4 gm = __ldg(((const float4*)gamma) + lane);
    float4 bt = __ldg(((const float4*)beta) + lane);
    float pw  = __ldg(prelu_w);

    int beg = g_off[node] + __ldg(&g_bsum[node >> 10]);   // scan3 fused here
    int deg = g_deg[node];
    float4 ad = __ldg((const float4*)(g_adst + node * NHEAD));  // warp-uniform sector
    float4 xv = __ldg(((const float4*)(x + (size_t)node * D)) + lane);  // hoisted residual

    float den = 0.f;
    float4 acc = make_float4(0.f, 0.f, 0.f, 0.f);

    for (int base = 0; base < deg; base += 32) {
        int cn = min(32, deg - base);
        if (lane < cn) {
            int s = __ldg(&g_csr[beg + base + lane]);
            float4 av = __ldg((const float4*)(g_asrc + s * NHEAD));
            float l0 = av.x + ad.x; l0 = l0 >= 0.f ? l0 : 0.2f * l0;
            float l1 = av.y + ad.y; l1 = l1 >= 0.f ? l1 : 0.2f * l1;
            float l2 = av.z + ad.z; l2 = l2 >= 0.f ? l2 : 0.2f * l2;
            float l3 = av.w + ad.w; l3 = l3 >= 0.f ? l3 : 0.2f * l3;
            wv_s[w][lane] = make_float4(__expf(l0), __expf(l1), __expf(l2), __expf(l3));
            ss_s[w][lane] = s;
        }
        __syncwarp();
        #pragma unroll 16
        for (int j = 0; j < cn; j++) {
            int s = ss_s[w][j];                               // smem broadcast
            float a = ((const float*)&wv_s[w][j])[head];      // smem (4-way bcast)
            uint2 hv = __ldg(((const uint2*)(g_h + (size_t)s * 64)) + lane); // 256B/warp
            float2 f01 = __half22float2(*(__half2*)&hv.x);
            float2 f23 = __half22float2(*(__half2*)&hv.y);
            den += a;
            acc.x += a * f01.x; acc.y += a * f01.y;
            acc.z += a * f23.x; acc.w += a * f23.y;
        }
        if (base + 32 < deg) __syncwarp();
    }

    float inv = (den > 0.f) ? (1.f / den) : 0.f;   // deg==0 -> 0 (matches ref)

    // LayerNorm over the warp's 128 channels (4 per lane)
    float4 v;
    v.x = acc.x * inv + bs.x; v.y = acc.y * inv + bs.y;
    v.z = acc.z * inv + bs.z; v.w = acc.w * inv + bs.w;
    float s1 = v.x + v.y + v.z + v.w;
    float s2 = v.x * v.x + v.y * v.y + v.z * v.z + v.w * v.w;
    #pragma unroll
    for (int o = 16; o > 0; o >>= 1) {
        s1 += __shfl_xor_sync(0xffffffffu, s1, o);
        s2 += __shfl_xor_sync(0xffffffffu, s2, o);
    }
    float mu = s1 * (1.f / 128.f);
    float var = fmaxf(s2 * (1.f / 128.f) - mu * mu, 0.f);
    float rs = rsqrtf(var + 1e-5f);

    float4 o4;
    float o;
    o = (v.x - mu) * rs * gm.x + bt.x; o = o >= 0.f ? o : pw * o; o4.x = o + xv.x;
    o = (v.y - mu) * rs * gm.y + bt.y; o = o >= 0.f ? o : pw * o; o4.y = o + xv.y;
    o = (v.z - mu) * rs * gm.z + bt.z; o = o >= 0.f ? o : pw * o; o4.z = o + xv.z;
    o = (v.w - mu) * rs * gm.w + bt.w; o = o >= 0.f ? o : pw * o; o4.w = o + xv.w;
    ((float4*)(out + (size_t)node * D))[lane] = o4;
}

// ---------------- launch: fork GEMM onto side stream, overlap with CSR build ----
extern "C" void kernel_launch(void* const* d_in, const int* in_sizes, int n_in,
                              void* d_out, int out_size) {
    const float* x       = (const float*)d_in[0];
    const void*  ei      = d_in[1];
    const float* W       = (const float*)d_in[2];
    const float* att_src = (const float*)d_in[3];
    const float* att_dst = (const float*)d_in[4];
    const float* bias    = (const float*)d_in[5];
    const float* gamma   = (const float*)d_in[6];
    const float* beta    = (const float*)d_in[7];
    const float* prelu   = (const float*)d_in[8];
    float* out = (float*)d_out;

    int n = in_sizes[0] / D;
    int E = in_sizes[1] / 2;
    int B = (n + 1023) / 1024;

    static cudaStream_t s2 = 0;
    static cudaEvent_t evFork = 0, evJoin = 0;
    static int init = 0;
    if (!init) {
        if (cudaStreamCreateWithFlags(&s2, cudaStreamNonBlocking) != cudaSuccess) s2 = 0;
        cudaEventCreateWithFlags(&evFork, cudaEventDisableTiming);
        cudaEventCreateWithFlags(&evJoin, cudaEventDisableTiming);
        init = 1;
    }

    bool fork = (s2 != 0);
    if (fork) {
        cudaEventRecord(evFork, 0);
        cudaStreamWaitEvent(s2, evFork, 0);
        k_gemm<<<(n + 63) / 64, 256, 0, s2>>>(x, W, att_src, att_dst, n);
        cudaEventRecord(evJoin, s2);
    }

    k_detect_zero<<<(n + 255) / 256, 256>>>(ei, n);
    k_extract<<<(E + 255) / 256, 256>>>(ei, E);
    k_scan1<<<B, 1024>>>(n);
    k_scan2<<<1, 1024>>>(B);
    k_scatter<<<(E + 255) / 256, 256>>>(E);

    if (fork) {
        cudaStreamWaitEvent(0, evJoin, 0);   // join before consumers of g_h/g_asrc
    } else {
        k_gemm<<<(n + 63) / 64, 256>>>(x, W, att_src, att_dst, n);
    }

    k_node<<<(n + 7) / 8, 256>>>(x, bias, gamma, beta, prelu, out, n);
}